// round 1
// baseline (speedup 1.0000x reference)
#include <cuda_runtime.h>
#include <cstdint>

// CSCFCLayer: out[b][n] = sum_{f<64} x[b][(n+f)%C] * kernel[(n+f)%C][n] + bias[n]
// B=128, C=N=8192, F=64, fp32.
//
// Strategy:
//  - Per block: NT=64 output columns (n0..n0+63), all B=128 batches. Grid = 128 blocks.
//  - Shared "c" loop (c = n+f, unwrapped offset cl in [0,127)): one x column feeds
//    64 outputs; weight kernel[(n0+cl)%C][n] loaded COALESCED per row (64 contiguous cols).
//  - Weights stored DUPLICATED as float2 in smem -> packed fp32x2 FMA without repacking.
//  - x stored as (x[b][c], x[b+64][c]) float2 pairs -> LDS.64 feeds the other FMA2 operand.
//  - Inner loop per c per thread: 2 LDS.64 + 4 LDS.128(broadcast) + 16 fma.rn.f32x2.
//  - Epilogue: smem transpose for coalesced fp32 output stores + bias add.

#define CDIM 8192
#define NDIM 8192
#define BDIM 128
#define FDIM 64
#define NT 64
#define NWARPS 8
#define THREADS 256
#define CROWS 127              // NT + FDIM - 1
#define WS_STRIDE_F 132        // floats per ws row (66 float2; 528B, 16B-aligned)
#define XS_STRIDE_F 130        // floats per xs row (65 float2; odd f2-stride -> 2-way write conflict max)

__device__ __forceinline__ void fma2(unsigned long long& d,
                                     unsigned long long a,
                                     unsigned long long b) {
    asm("fma.rn.f32x2 %0, %1, %2, %0;" : "+l"(d) : "l"(a), "l"(b));
}

extern "C" __global__ void __launch_bounds__(THREADS, 1)
cscfc_kernel(const float* __restrict__ x,
             const float* __restrict__ w,
             const float* __restrict__ bias,
             float* __restrict__ out)
{
    extern __shared__ float smem[];
    float* ws = smem;                         // CROWS * WS_STRIDE_F floats (dup'd band weights)
    float* xs = smem + CROWS * WS_STRIDE_F;   // CROWS * XS_STRIDE_F floats (paired x)

    const int tid  = threadIdx.x;
    const int lane = tid & 31;
    const int ng   = tid >> 5;                // warp id = n-group
    const int n0   = blockIdx.x * NT;

    // ---- Fill ws: row cl holds kernel[(n0+cl)%C][n0+nl] duplicated at float2 slot nl,
    //      zero where f = cl - nl is outside [0,64). Coalesced 256B row reads. ----
    for (int cl = ng; cl < CROWS; cl += NWARPS) {
        const int r = (n0 + cl) & (CDIM - 1);
        const float* krow = w + (size_t)r * NDIM + n0;
        const float k0 = krow[lane];
        const float k1 = krow[lane + 32];
        const int f0 = cl - lane;
        const int f1 = cl - (lane + 32);
        const float v0 = (f0 >= 0 && f0 < FDIM) ? k0 : 0.0f;
        const float v1 = (f1 >= 0 && f1 < FDIM) ? k1 : 0.0f;
        float2* wrow = (float2*)(ws + cl * WS_STRIDE_F);
        wrow[lane]      = make_float2(v0, v0);
        wrow[lane + 32] = make_float2(v1, v1);
    }

    // ---- Fill xs: xs[cl] pair q = (x[q][c], x[q+64][c]), c = (n0+cl)%C.
    //      Coalesced gmem reads (consecutive cl per lane). ----
    for (int idx = tid; idx < BDIM * 128; idx += THREADS) {
        const int b  = idx >> 7;
        const int cl = idx & 127;
        if (cl < CROWS) {
            const float v = x[(size_t)b * CDIM + ((n0 + cl) & (CDIM - 1))];
            const int q = b & 63;
            const int h = b >> 6;
            xs[cl * XS_STRIDE_F + q * 2 + h] = v;
        }
    }
    __syncthreads();

    // ---- Compute: warp ng owns columns n0+ng*8 .. +7; private c window of 71 steps. ----
    unsigned long long accA[8], accB[8];
#pragma unroll
    for (int j = 0; j < 8; ++j) { accA[j] = 0ULL; accB[j] = 0ULL; }

    const int cl_lo = ng * 8;
    const int cl_hi = ng * 8 + 70;
#pragma unroll 2
    for (int cl = cl_lo; cl <= cl_hi; ++cl) {
        const float* xrow = xs + cl * XS_STRIDE_F;
        const unsigned long long x0 =
            *(const unsigned long long*)(xrow + lane * 2);        // (b=lane,   b=lane+64)
        const unsigned long long x1 =
            *(const unsigned long long*)(xrow + 64 + lane * 2);   // (b=lane+32,b=lane+96)
        const ulonglong2* wv = (const ulonglong2*)(ws + cl * WS_STRIDE_F) + ng * 4;
#pragma unroll
        for (int k = 0; k < 4; ++k) {
            const ulonglong2 wp = wv[k];     // LDS.128 broadcast: 2 duplicated weight pairs
            fma2(accA[2 * k],     x0, wp.x);
            fma2(accB[2 * k],     x1, wp.x);
            fma2(accA[2 * k + 1], x0, wp.y);
            fma2(accB[2 * k + 1], x1, wp.y);
        }
    }
    __syncthreads();

    // ---- Epilogue: stage to smem (conflict-free), then coalesced stores + bias. ----
    float* os = smem;  // [128 b][65] floats, aliases ws region
#pragma unroll
    for (int j = 0; j < 8; ++j) {
        const int nl = ng * 8 + j;
        os[(lane)      * 65 + nl] = __uint_as_float((unsigned)(accA[j] & 0xffffffffu));
        os[(lane + 64) * 65 + nl] = __uint_as_float((unsigned)(accA[j] >> 32));
        os[(lane + 32) * 65 + nl] = __uint_as_float((unsigned)(accB[j] & 0xffffffffu));
        os[(lane + 96) * 65 + nl] = __uint_as_float((unsigned)(accB[j] >> 32));
    }
    __syncthreads();

    for (int t = tid; t < BDIM * NT; t += THREADS) {
        const int nl = t & 63;
        const int b  = t >> 6;
        out[(size_t)b * NDIM + n0 + nl] = os[b * 65 + nl] + bias[n0 + nl];
    }
}

extern "C" void kernel_launch(void* const* d_in, const int* in_sizes, int n_in,
                              void* d_out, int out_size) {
    const float* x    = (const float*)d_in[0];
    const float* w    = (const float*)d_in[1];
    const float* bias = (const float*)d_in[2];
    float* out        = (float*)d_out;

    const size_t smem_bytes =
        (size_t)(CROWS * WS_STRIDE_F + CROWS * XS_STRIDE_F) * sizeof(float);
    cudaFuncSetAttribute(cscfc_kernel,
                         cudaFuncAttributeMaxDynamicSharedMemorySize,
                         (int)smem_bytes);
    cscfc_kernel<<<NDIM / NT, THREADS, smem_bytes>>>(x, w, bias, out);
}

// round 2
// speedup vs baseline: 1.3409x; 1.3409x over previous
#include <cuda_runtime.h>
#include <cstdint>

// CSCFCLayer: out[b][n] = sum_{f<64} x[b][(n+f)%C] * kernel[(n+f)%C][n] + bias[n]
// B=128, C=N=8192, F=64, fp32.
//
// v2: 512 threads (16 warps), 2-way c-window split per 8-column warp group.
//  - Per block: NT=64 output columns, all 128 batches. Grid = 128.
//  - Warp (ng, half): cols n0+ng*8..+7, c-steps [ng*8 + half*36, +36).
//  - Weights duplicated as float2 in smem -> fma.rn.f32x2 without repacking.
//  - x paired over batch halves -> LDS.64 operands.
//  - Epilogue: half-0 writes partials to smem, half-1 adds, coalesced store + bias.

#define CDIM 8192
#define NDIM 8192
#define BDIM 128
#define FDIM 64
#define NT 64
#define THREADS 512
#define NWARPS 16
#define CROWS 128              // NT + FDIM (row 127 = all-zero pad via band mask)
#define WS_STRIDE_F 132        // floats per ws row (66 float2; 528B, 16B aligned)
#define XS_STRIDE_F 130        // floats per xs row (65 float2)
#define HALF_STEPS 36

__device__ __forceinline__ void fma2(unsigned long long& d,
                                     unsigned long long a,
                                     unsigned long long b) {
    asm("fma.rn.f32x2 %0, %1, %2, %0;" : "+l"(d) : "l"(a), "l"(b));
}

extern "C" __global__ void __launch_bounds__(THREADS, 1)
cscfc_kernel(const float* __restrict__ x,
             const float* __restrict__ w,
             const float* __restrict__ bias,
             float* __restrict__ out)
{
    extern __shared__ float smem[];
    float* ws = smem;                         // CROWS * WS_STRIDE_F (dup'd band weights)
    float* xs = smem + CROWS * WS_STRIDE_F;   // CROWS * XS_STRIDE_F (paired x)

    const int tid  = threadIdx.x;
    const int lane = tid & 31;
    const int wid  = tid >> 5;                // 0..15
    const int ng   = wid & 7;                 // column group
    const int half = wid >> 3;                // c-window half
    const int n0   = blockIdx.x * NT;

    // ---- ws fill: row cl holds kernel[(n0+cl)%C][n0+nl] duplicated at f2 slot nl,
    //      zeroed where f = cl - nl outside [0,64). Coalesced 256B row reads. ----
    for (int cl = wid; cl < CROWS; cl += NWARPS) {
        const int r = (n0 + cl) & (CDIM - 1);
        const float* krow = w + (size_t)r * NDIM + n0;
        const float k0 = krow[lane];
        const float k1 = krow[lane + 32];
        const int f0 = cl - lane;
        const int f1 = cl - (lane + 32);
        const float v0 = (f0 >= 0 && f0 < FDIM) ? k0 : 0.0f;
        const float v1 = (f1 >= 0 && f1 < FDIM) ? k1 : 0.0f;
        float2* wrow = (float2*)(ws + cl * WS_STRIDE_F);
        wrow[lane]      = make_float2(v0, v0);
        wrow[lane + 32] = make_float2(v1, v1);
    }

    // ---- xs fill: xs[cl] f2-slot q = (x[q][c], x[q+64][c]), c = (n0+cl)%C. ----
#pragma unroll 4
    for (int idx = tid; idx < BDIM * CROWS; idx += THREADS) {
        const int b  = idx >> 7;              // CROWS == 128
        const int cl = idx & (CROWS - 1);
        const float v = x[(size_t)b * CDIM + ((n0 + cl) & (CDIM - 1))];
        const int q = b & 63;
        const int h = b >> 6;
        xs[cl * XS_STRIDE_F + q * 2 + h] = v;
    }
    __syncthreads();

    // ---- Compute: 36 uniform steps per warp. ----
    unsigned long long accA[8], accB[8];
#pragma unroll
    for (int j = 0; j < 8; ++j) { accA[j] = 0ULL; accB[j] = 0ULL; }

    const int cl0 = ng * 8 + half * HALF_STEPS;
#pragma unroll 4
    for (int i = 0; i < HALF_STEPS; ++i) {
        const int cl = cl0 + i;
        const float* xrow = xs + cl * XS_STRIDE_F;
        const unsigned long long x0 =
            *(const unsigned long long*)(xrow + lane * 2);        // (b=lane,   b=lane+64)
        const unsigned long long x1 =
            *(const unsigned long long*)(xrow + 64 + lane * 2);   // (b=lane+32,b=lane+96)
        const ulonglong2* wv = (const ulonglong2*)(ws + cl * WS_STRIDE_F) + ng * 4;
#pragma unroll
        for (int k = 0; k < 4; ++k) {
            const ulonglong2 wp = wv[k];      // LDS.128 broadcast (2 dup'd weight pairs)
            fma2(accA[2 * k],     x0, wp.x);
            fma2(accB[2 * k],     x1, wp.x);
            fma2(accA[2 * k + 1], x0, wp.y);
            fma2(accB[2 * k + 1], x1, wp.y);
        }
    }
    __syncthreads();

    // ---- Epilogue: half-0 writes partials, half-1 accumulates, then store. ----
    float* os = smem;   // [128 b][65] floats, aliases ws/xs region
    if (half == 0) {
#pragma unroll
        for (int j = 0; j < 8; ++j) {
            const int nl = ng * 8 + j;
            os[(lane)      * 65 + nl] = __uint_as_float((unsigned)(accA[j] & 0xffffffffu));
            os[(lane + 64) * 65 + nl] = __uint_as_float((unsigned)(accA[j] >> 32));
            os[(lane + 32) * 65 + nl] = __uint_as_float((unsigned)(accB[j] & 0xffffffffu));
            os[(lane + 96) * 65 + nl] = __uint_as_float((unsigned)(accB[j] >> 32));
        }
    }
    __syncthreads();
    if (half == 1) {
#pragma unroll
        for (int j = 0; j < 8; ++j) {
            const int nl = ng * 8 + j;
            os[(lane)      * 65 + nl] += __uint_as_float((unsigned)(accA[j] & 0xffffffffu));
            os[(lane + 64) * 65 + nl] += __uint_as_float((unsigned)(accA[j] >> 32));
            os[(lane + 32) * 65 + nl] += __uint_as_float((unsigned)(accB[j] & 0xffffffffu));
            os[(lane + 96) * 65 + nl] += __uint_as_float((unsigned)(accB[j] >> 32));
        }
    }
    __syncthreads();

#pragma unroll 4
    for (int t = tid; t < BDIM * NT; t += THREADS) {
        const int nl = t & (NT - 1);
        const int b  = t >> 6;
        out[(size_t)b * NDIM + n0 + nl] = os[b * 65 + nl] + bias[n0 + nl];
    }
}

extern "C" void kernel_launch(void* const* d_in, const int* in_sizes, int n_in,
                              void* d_out, int out_size) {
    const float* x    = (const float*)d_in[0];
    const float* w    = (const float*)d_in[1];
    const float* bias = (const float*)d_in[2];
    float* out        = (float*)d_out;

    const size_t smem_bytes =
        (size_t)(CROWS * WS_STRIDE_F + CROWS * XS_STRIDE_F) * sizeof(float);
    cudaFuncSetAttribute(cscfc_kernel,
                         cudaFuncAttributeMaxDynamicSharedMemorySize,
                         (int)smem_bytes);
    cscfc_kernel<<<NDIM / NT, THREADS, smem_bytes>>>(x, w, bias, out);
}